// round 3
// baseline (speedup 1.0000x reference)
#include <cuda_runtime.h>
#include <cuda_bf16.h>

#define BB 16
#define CC 528
#define TT 32
#define HH 28
#define WW 28
#define HW 784          // 28*28
#define HW4 196         // HW/4
#define RR 256
#define PLANE_F (TT*HW) // 25088 floats per (b,c)

// ---- device scratch (no allocations allowed) ----
__device__ float g_wmap[RR * HW];     // per-ROI dense weight map over 28x28
__device__ int4  g_rect[RR];          // x: xmin, y: xmax, z: ymin, w: ymax (inclusive), xmin>xmax => empty
__device__ int   g_list[BB][RR];      // ROI indices per batch
__device__ int   g_cnt[BB];
__device__ float g_rmean[RR * CC];    // pooled ROI features

// ============================================================
// Kernel 0: build per-ROI weight map + nonzero rect.
// 256 blocks (one per ROI), 256 threads (one per sample point).
// ============================================================
__global__ void wmap_kernel(const float* __restrict__ bbox) {
    __shared__ float smap[HW];
    __shared__ int sxmin, sxmax, symin, symax;
    const int roi = blockIdx.x;
    const int tid = threadIdx.x;

    for (int p = tid; p < HW; p += 256) smap[p] = 0.f;
    if (tid == 0) { sxmin = 1000; symin = 1000; sxmax = -1; symax = -1; }
    __syncthreads();

    const float* bb = bbox + roi * 5;
    const float x1 = bb[1] * 0.0625f - 0.5f;
    const float y1 = bb[2] * 0.0625f - 0.5f;
    const float x2 = bb[3] * 0.0625f - 0.5f;
    const float y2 = bb[4] * 0.0625f - 0.5f;
    const float bw = (x2 - x1) * 0.125f;   // /OUT(8)
    const float bh = (y2 - y1) * 0.125f;

    const int iy = tid >> 4, ix = tid & 15;
    const float sy = y1 + ((float)iy * 0.5f + 0.25f) * bh;  // off=(i+0.5)/SR
    const float sx = x1 + ((float)ix * 0.5f + 0.25f) * bw;

    const bool valid = (sy > -1.0f) && (sy < (float)HH) && (sx > -1.0f) && (sx < (float)WW);
    if (valid) {
        float yc = fminf(fmaxf(sy, 0.f), (float)(HH - 1));
        float xc = fminf(fmaxf(sx, 0.f), (float)(WW - 1));
        int y0 = (int)floorf(yc);
        int x0 = (int)floorf(xc);
        int y1i = min(y0 + 1, HH - 1);
        int x1i = min(x0 + 1, WW - 1);
        float ly = yc - (float)y0, lx = xc - (float)x0;
        float hy = 1.f - ly, hx = 1.f - lx;
        const float s = 1.0f / 256.0f;   // uniform mean over 16x16 samples
        atomicAdd(&smap[y0 * WW + x0],  hy * hx * s);
        atomicAdd(&smap[y0 * WW + x1i], hy * lx * s);
        atomicAdd(&smap[y1i * WW + x0], ly * hx * s);
        atomicAdd(&smap[y1i * WW + x1i], ly * lx * s);
        atomicMin(&sxmin, x0); atomicMax(&sxmax, x1i);
        atomicMin(&symin, y0); atomicMax(&symax, y1i);
    }
    __syncthreads();

    for (int p = tid; p < HW; p += 256) g_wmap[roi * HW + p] = smap[p];
    if (tid == 0) g_rect[roi] = make_int4(sxmin, sxmax, symin, symax);
}

// ============================================================
// Kernel 1: per-batch ROI lists (deterministic, 16 threads).
// ============================================================
__global__ void list_kernel(const float* __restrict__ bbox) {
    int b = threadIdx.x;
    if (b >= BB) return;
    int cnt = 0;
    for (int r = 0; r < RR; ++r) {
        int rb = (int)bbox[r * 5];
        if (rb == b) g_list[b][cnt++] = r;
    }
    g_cnt[b] = cnt;
}

// ============================================================
// Kernel 2 (the HBM-bound one): fused temporal mean + ROI pooling.
// One block per (b,c) pair: 8448 blocks, 256 threads.
//   phase 1: plane[p] = mean_t x[b,c,t,p]   (float4, coalesced)
//   phase 2: per-warp dot(Wmap[roi] restricted to rect, plane)
// ============================================================
__global__ void __launch_bounds__(256) mean_roi_kernel(const float* __restrict__ x) {
    __shared__ float plane[HW];
    const int blk = blockIdx.x;            // b*CC + c
    const int b = blk / CC;
    const int c = blk - b * CC;
    const int tid = threadIdx.x;

    const float4* __restrict__ xp =
        (const float4*)(x + (size_t)blk * PLANE_F);

    if (tid < HW4) {
        float ax = 0.f, ay = 0.f, az = 0.f, aw = 0.f;
        #pragma unroll
        for (int t = 0; t < TT; ++t) {
            float4 v = xp[t * HW4 + tid];
            ax += v.x; ay += v.y; az += v.z; aw += v.w;
        }
        const float inv = 1.0f / (float)TT;
        ((float4*)plane)[tid] = make_float4(ax * inv, ay * inv, az * inv, aw * inv);
    }
    __syncthreads();

    const int nroi = g_cnt[b];
    const int warp = tid >> 5, lane = tid & 31;
    for (int r = warp; r < nroi; r += 8) {
        const int roi = g_list[b][r];
        const int4 rc = g_rect[roi];       // xmin xmax ymin ymax
        float acc = 0.f;
        if (rc.x <= rc.y) {
            const int w = rc.y - rc.x + 1;
            const int n = w * (rc.w - rc.z + 1);
            const float* __restrict__ wm = g_wmap + roi * HW;
            for (int k = lane; k < n; k += 32) {
                int yy = rc.z + k / w;
                int xx = rc.x + k - (k / w) * w;
                int p = yy * WW + xx;
                acc += wm[p] * plane[p];
            }
        }
        #pragma unroll
        for (int o = 16; o; o >>= 1) acc += __shfl_xor_sync(0xffffffffu, acc, o);
        if (lane == 0) g_rmean[roi * CC + c] = acc;
    }
}

// ============================================================
// Kernel 3: tiny MLP head. One block per ROI, 128 threads.
// h1 = relu(r @ w1^T + b1); h2 = h1 @ w2^T + b2; out = h2 @ w3^T + b3
// ============================================================
__global__ void __launch_bounds__(128) mlp_kernel(
    const float* __restrict__ w1, const float* __restrict__ b1,
    const float* __restrict__ w2, const float* __restrict__ b2,
    const float* __restrict__ w3, const float* __restrict__ b3,
    float* __restrict__ out) {
    __shared__ float r[CC];
    __shared__ float h1[128];
    __shared__ float h2[32];
    const int roi = blockIdx.x;
    const int tid = threadIdx.x;

    for (int k = tid; k < CC; k += 128) r[k] = g_rmean[roi * CC + k];
    __syncthreads();

    {
        float acc = b1[tid];
        const float* __restrict__ wr = w1 + tid * CC;
        #pragma unroll 8
        for (int k = 0; k < CC; ++k) acc += wr[k] * r[k];
        h1[tid] = fmaxf(acc, 0.f);
    }
    __syncthreads();

    if (tid < 32) {
        float acc = b2[tid];
        const float* __restrict__ wr = w2 + tid * 128;
        #pragma unroll 8
        for (int k = 0; k < 128; ++k) acc += wr[k] * h1[k];
        h2[tid] = acc;
    }
    __syncthreads();

    if (tid < 32) {
        float v = h2[tid] * w3[tid];
        #pragma unroll
        for (int o = 16; o; o >>= 1) v += __shfl_xor_sync(0xffffffffu, v, o);
        if (tid == 0) out[roi] = v + b3[0];
    }
}

// ============================================================
// launch
// ============================================================
extern "C" void kernel_launch(void* const* d_in, const int* in_sizes, int n_in,
                              void* d_out, int out_size) {
    const float* x    = (const float*)d_in[0];
    const float* bbox = (const float*)d_in[1];
    const float* w1   = (const float*)d_in[2];
    const float* b1   = (const float*)d_in[3];
    const float* w2   = (const float*)d_in[4];
    const float* b2   = (const float*)d_in[5];
    const float* w3   = (const float*)d_in[6];
    const float* b3   = (const float*)d_in[7];
    float* out = (float*)d_out;

    wmap_kernel<<<RR, 256>>>(bbox);
    list_kernel<<<1, 32>>>(bbox);
    mean_roi_kernel<<<BB * CC, 256>>>(x);
    mlp_kernel<<<RR, 128>>>(w1, b1, w2, b2, w3, b3, out);
}

// round 4
// speedup vs baseline: 1.1146x; 1.1146x over previous
#include <cuda_runtime.h>
#include <cuda_bf16.h>

#define BB 16
#define CC 528
#define TT 32
#define HH 28
#define WW 28
#define HW 784          // 28*28
#define HW4 196         // HW/4
#define RR 256
#define PLANE_F (TT*HW) // 25088 floats per (b,c)

// ---- device scratch (no allocations allowed) ----
__device__ float g_wmap[RR * HW];     // per-ROI dense weight map over 28x28
__device__ int4  g_rect[RR];          // x: xmin, y: xmax, z: ymin, w: ymax (inclusive); xmin>xmax => empty
__device__ int   g_list[BB][RR];      // ROI indices per batch
__device__ int   g_cnt[BB];
__device__ float g_rmean[RR * CC];    // pooled ROI features
__device__ float g_v[128];            // folded w3 @ w2   (layers 2+3 are linear)
__device__ float g_c0;                // folded bias

// ============================================================
// Kernel 0: build per-ROI weight map + nonzero rect.
// ============================================================
__global__ void wmap_kernel(const float* __restrict__ bbox) {
    __shared__ float smap[HW];
    __shared__ int sxmin, sxmax, symin, symax;
    const int roi = blockIdx.x;
    const int tid = threadIdx.x;

    for (int p = tid; p < HW; p += 256) smap[p] = 0.f;
    if (tid == 0) { sxmin = 1000; symin = 1000; sxmax = -1; symax = -1; }
    __syncthreads();

    const float* bb = bbox + roi * 5;
    const float x1 = bb[1] * 0.0625f - 0.5f;
    const float y1 = bb[2] * 0.0625f - 0.5f;
    const float x2 = bb[3] * 0.0625f - 0.5f;
    const float y2 = bb[4] * 0.0625f - 0.5f;
    const float bw = (x2 - x1) * 0.125f;   // /OUT(8)
    const float bh = (y2 - y1) * 0.125f;

    const int iy = tid >> 4, ix = tid & 15;
    const float sy = y1 + ((float)iy * 0.5f + 0.25f) * bh;  // off=(i+0.5)/SR
    const float sx = x1 + ((float)ix * 0.5f + 0.25f) * bw;

    const bool valid = (sy > -1.0f) && (sy < (float)HH) && (sx > -1.0f) && (sx < (float)WW);
    if (valid) {
        float yc = fminf(fmaxf(sy, 0.f), (float)(HH - 1));
        float xc = fminf(fmaxf(sx, 0.f), (float)(WW - 1));
        int y0 = (int)floorf(yc);
        int x0 = (int)floorf(xc);
        int y1i = min(y0 + 1, HH - 1);
        int x1i = min(x0 + 1, WW - 1);
        float ly = yc - (float)y0, lx = xc - (float)x0;
        float hy = 1.f - ly, hx = 1.f - lx;
        const float s = 1.0f / 256.0f;   // uniform mean over 16x16 samples
        atomicAdd(&smap[y0 * WW + x0],  hy * hx * s);
        atomicAdd(&smap[y0 * WW + x1i], hy * lx * s);
        atomicAdd(&smap[y1i * WW + x0], ly * hx * s);
        atomicAdd(&smap[y1i * WW + x1i], ly * lx * s);
        atomicMin(&sxmin, x0); atomicMax(&sxmax, x1i);
        atomicMin(&symin, y0); atomicMax(&symax, y1i);
    }
    __syncthreads();

    for (int p = tid; p < HW; p += 256) g_wmap[roi * HW + p] = smap[p];
    if (tid == 0) g_rect[roi] = make_int4(sxmin, sxmax, symin, symax);
}

// ============================================================
// Kernel 1: per-batch ROI lists (deterministic) + folded v = w3@w2.
// block 0: lists (threads 0..15). block 1: v (threads 0..127).
// ============================================================
__global__ void prep_kernel(const float* __restrict__ bbox,
                            const float* __restrict__ w2,
                            const float* __restrict__ b2,
                            const float* __restrict__ w3,
                            const float* __restrict__ b3) {
    if (blockIdx.x == 0) {
        int b = threadIdx.x;
        if (b < BB) {
            int cnt = 0;
            for (int r = 0; r < RR; ++r) {
                int rb = (int)bbox[r * 5];
                if (rb == b) g_list[b][cnt++] = r;
            }
            g_cnt[b] = cnt;
        }
    } else {
        int j = threadIdx.x;
        if (j < 128) {
            float acc = 0.f;
            #pragma unroll
            for (int i = 0; i < 32; ++i) acc += w3[i] * w2[i * 128 + j];
            g_v[j] = acc;
            if (j == 0) {
                float c = b3[0];
                #pragma unroll
                for (int i = 0; i < 32; ++i) c += w3[i] * b2[i];
                g_c0 = c;
            }
        }
    }
}

// ============================================================
// Kernel 2 (HBM-bound): fused temporal mean + ROI pooling.
// One block per (b,c): 8448 blocks, 256 threads.
// ============================================================
__global__ void __launch_bounds__(256) mean_roi_kernel(const float* __restrict__ x) {
    __shared__ float plane[HW];
    const int blk = blockIdx.x;            // b*CC + c
    const int b = blk / CC;
    const int c = blk - b * CC;
    const int tid = threadIdx.x;

    const float4* __restrict__ xp =
        (const float4*)(x + (size_t)blk * PLANE_F);

    if (tid < HW4) {
        float ax = 0.f, ay = 0.f, az = 0.f, aw = 0.f;
        #pragma unroll
        for (int t = 0; t < TT; ++t) {
            float4 v = __ldcs(&xp[t * HW4 + tid]);   // streaming: don't pollute L2
            ax += v.x; ay += v.y; az += v.z; aw += v.w;
        }
        const float inv = 1.0f / (float)TT;
        ((float4*)plane)[tid] = make_float4(ax * inv, ay * inv, az * inv, aw * inv);
    }
    __syncthreads();

    const int nroi = g_cnt[b];
    const int warp = tid >> 5, lane = tid & 31;
    for (int r = warp; r < nroi; r += 8) {
        const int roi = g_list[b][r];
        const int4 rc = g_rect[roi];       // xmin xmax ymin ymax
        float acc = 0.f;
        if (rc.x <= rc.y) {
            // width <= 28 < 32: one element per lane per row, no int division
            const int xx = rc.x + lane;
            const bool on = (xx <= rc.y);
            const float* __restrict__ wm = g_wmap + roi * HW;
            for (int yy = rc.z; yy <= rc.w; ++yy) {
                int p = yy * WW + xx;
                if (on) acc += wm[p] * plane[p];
            }
        }
        #pragma unroll
        for (int o = 16; o; o >>= 1) acc += __shfl_xor_sync(0xffffffffu, acc, o);
        if (lane == 0) g_rmean[roi * CC + c] = acc;
    }
}

// ============================================================
// Kernel 3: fused MLP head: out[roi] = c0 + sum_j v[j]*relu(r.w1_j + b1_j)
// grid 128 blocks x 2 ROIs; 8 warps; warp-per-neuron, lane-strided k (coalesced).
// ============================================================
__global__ void __launch_bounds__(256) mlp_kernel(
    const float* __restrict__ w1, const float* __restrict__ b1,
    float* __restrict__ out) {
    __shared__ float r0[CC], r1[CC];
    __shared__ float part[2][8];
    const int tid = threadIdx.x, warp = tid >> 5, lane = tid & 31;
    const int roi0 = blockIdx.x * 2;

    for (int k = tid; k < CC; k += 256) {
        r0[k] = g_rmean[roi0 * CC + k];
        r1[k] = g_rmean[(roi0 + 1) * CC + k];
    }
    __syncthreads();

    float o0 = 0.f, o1 = 0.f;
    for (int j = warp; j < 128; j += 8) {
        const float* __restrict__ wr = w1 + j * CC;
        float a0 = 0.f, a1 = 0.f;
        #pragma unroll 4
        for (int k = lane; k < CC; k += 32) {
            float w = wr[k];
            a0 += w * r0[k];
            a1 += w * r1[k];
        }
        #pragma unroll
        for (int o = 16; o; o >>= 1) {
            a0 += __shfl_xor_sync(0xffffffffu, a0, o);
            a1 += __shfl_xor_sync(0xffffffffu, a1, o);
        }
        float bj = b1[j], vj = g_v[j];
        o0 += vj * fmaxf(a0 + bj, 0.f);
        o1 += vj * fmaxf(a1 + bj, 0.f);
    }
    if (lane == 0) { part[0][warp] = o0; part[1][warp] = o1; }
    __syncthreads();
    if (tid < 2) {
        float s = g_c0;
        #pragma unroll
        for (int w = 0; w < 8; ++w) s += part[tid][w];
        out[roi0 + tid] = s;
    }
}

// ============================================================
// launch
// ============================================================
extern "C" void kernel_launch(void* const* d_in, const int* in_sizes, int n_in,
                              void* d_out, int out_size) {
    const float* x    = (const float*)d_in[0];
    const float* bbox = (const float*)d_in[1];
    const float* w1   = (const float*)d_in[2];
    const float* b1   = (const float*)d_in[3];
    const float* w2   = (const float*)d_in[4];
    const float* b2   = (const float*)d_in[5];
    const float* w3   = (const float*)d_in[6];
    const float* b3   = (const float*)d_in[7];
    float* out = (float*)d_out;

    wmap_kernel<<<RR, 256>>>(bbox);
    prep_kernel<<<2, 128>>>(bbox, w2, b2, w3, b3);
    mean_roi_kernel<<<BB * CC, 256>>>(x);
    mlp_kernel<<<RR / 2, 256>>>(w1, b1, out);
}

// round 5
// speedup vs baseline: 1.2216x; 1.0960x over previous
#include <cuda_runtime.h>
#include <cuda_bf16.h>

#define BB 16
#define CC 528
#define TT 32
#define HH 28
#define WW 28
#define HW 784          // 28*28
#define HW4 196         // HW/4
#define RR 256
#define PLANE_F (TT*HW) // 25088 floats per (b,c)

// ---- device scratch (no allocations allowed) ----
__device__ float g_wmap[RR * HW];     // per-ROI dense weight map over 28x28
__device__ int4  g_rect[RR];          // xmin, xmax, ymin, ymax (inclusive); xmin>xmax => empty
__device__ int   g_list[BB][RR];      // ROI indices per batch
__device__ int   g_cnt[BB];
__device__ float g_rmean[RR * CC];    // pooled ROI features
__device__ float g_v[128];            // folded w3 @ w2   (layers 2+3 are linear)
__device__ float g_c0;                // folded bias
__device__ float g_part[RR * 8];      // per-(roi, j-group) partial sums

// ============================================================
// Kernel 0: build per-ROI weight map + nonzero rect.
// ============================================================
__global__ void wmap_kernel(const float* __restrict__ bbox) {
    __shared__ float smap[HW];
    __shared__ int sxmin, sxmax, symin, symax;
    const int roi = blockIdx.x;
    const int tid = threadIdx.x;

    for (int p = tid; p < HW; p += 256) smap[p] = 0.f;
    if (tid == 0) { sxmin = 1000; symin = 1000; sxmax = -1; symax = -1; }
    __syncthreads();

    const float* bb = bbox + roi * 5;
    const float x1 = bb[1] * 0.0625f - 0.5f;
    const float y1 = bb[2] * 0.0625f - 0.5f;
    const float x2 = bb[3] * 0.0625f - 0.5f;
    const float y2 = bb[4] * 0.0625f - 0.5f;
    const float bw = (x2 - x1) * 0.125f;   // /OUT(8)
    const float bh = (y2 - y1) * 0.125f;

    const int iy = tid >> 4, ix = tid & 15;
    const float sy = y1 + ((float)iy * 0.5f + 0.25f) * bh;  // off=(i+0.5)/SR
    const float sx = x1 + ((float)ix * 0.5f + 0.25f) * bw;

    const bool valid = (sy > -1.0f) && (sy < (float)HH) && (sx > -1.0f) && (sx < (float)WW);
    if (valid) {
        float yc = fminf(fmaxf(sy, 0.f), (float)(HH - 1));
        float xc = fminf(fmaxf(sx, 0.f), (float)(WW - 1));
        int y0 = (int)floorf(yc);
        int x0 = (int)floorf(xc);
        int y1i = min(y0 + 1, HH - 1);
        int x1i = min(x0 + 1, WW - 1);
        float ly = yc - (float)y0, lx = xc - (float)x0;
        float hy = 1.f - ly, hx = 1.f - lx;
        const float s = 1.0f / 256.0f;   // uniform mean over 16x16 samples
        atomicAdd(&smap[y0 * WW + x0],  hy * hx * s);
        atomicAdd(&smap[y0 * WW + x1i], hy * lx * s);
        atomicAdd(&smap[y1i * WW + x0], ly * hx * s);
        atomicAdd(&smap[y1i * WW + x1i], ly * lx * s);
        atomicMin(&sxmin, x0); atomicMax(&sxmax, x1i);
        atomicMin(&symin, y0); atomicMax(&symax, y1i);
    }
    __syncthreads();

    for (int p = tid; p < HW; p += 256) g_wmap[roi * HW + p] = smap[p];
    if (tid == 0) g_rect[roi] = make_int4(sxmin, sxmax, symin, symax);
}

// ============================================================
// Kernel 1: per-batch ROI lists + folded v = w3@w2, c0 = w3@b2 + b3.
// ============================================================
__global__ void prep_kernel(const float* __restrict__ bbox,
                            const float* __restrict__ w2,
                            const float* __restrict__ b2,
                            const float* __restrict__ w3,
                            const float* __restrict__ b3) {
    if (blockIdx.x == 0) {
        int b = threadIdx.x;
        if (b < BB) {
            int cnt = 0;
            for (int r = 0; r < RR; ++r) {
                int rb = (int)bbox[r * 5];
                if (rb == b) g_list[b][cnt++] = r;
            }
            g_cnt[b] = cnt;
        }
    } else {
        int j = threadIdx.x;
        if (j < 128) {
            float acc = 0.f;
            #pragma unroll
            for (int i = 0; i < 32; ++i) acc += w3[i] * w2[i * 128 + j];
            g_v[j] = acc;
            if (j == 0) {
                float c = b3[0];
                #pragma unroll
                for (int i = 0; i < 32; ++i) c += w3[i] * b2[i];
                g_c0 = c;
            }
        }
    }
}

// ============================================================
// Kernel 2 (HBM-bound, at roofline): fused temporal mean + ROI pooling.
// One block per (b,c): 8448 blocks, 256 threads.
// ============================================================
__global__ void __launch_bounds__(256) mean_roi_kernel(const float* __restrict__ x) {
    __shared__ float plane[HW];
    const int blk = blockIdx.x;            // b*CC + c
    const int b = blk / CC;
    const int c = blk - b * CC;
    const int tid = threadIdx.x;

    const float4* __restrict__ xp =
        (const float4*)(x + (size_t)blk * PLANE_F);

    if (tid < HW4) {
        float ax = 0.f, ay = 0.f, az = 0.f, aw = 0.f;
        #pragma unroll
        for (int t = 0; t < TT; ++t) {
            float4 v = __ldcs(&xp[t * HW4 + tid]);   // streaming: don't pollute L2
            ax += v.x; ay += v.y; az += v.z; aw += v.w;
        }
        const float inv = 1.0f / (float)TT;
        ((float4*)plane)[tid] = make_float4(ax * inv, ay * inv, az * inv, aw * inv);
    }
    __syncthreads();

    const int nroi = g_cnt[b];
    const int warp = tid >> 5, lane = tid & 31;
    for (int r = warp; r < nroi; r += 8) {
        const int roi = g_list[b][r];
        const int4 rc = g_rect[roi];       // xmin xmax ymin ymax
        float acc = 0.f;
        if (rc.x <= rc.y) {
            // width <= 28 < 32: one element per lane per row
            const int xx = rc.x + lane;
            const bool on = (xx <= rc.y);
            const float* __restrict__ wm = g_wmap + roi * HW;
            for (int yy = rc.z; yy <= rc.w; ++yy) {
                int p = yy * WW + xx;
                if (on) acc += wm[p] * plane[p];
            }
        }
        #pragma unroll
        for (int o = 16; o; o >>= 1) acc += __shfl_xor_sync(0xffffffffu, acc, o);
        if (lane == 0) g_rmean[roi * CC + c] = acc;
    }
}

// ============================================================
// Kernel 3: layer-1 GEMV partials with 8-way j-split for occupancy.
// grid = (64 roi-quads, 8 j-groups), 256 threads (8 warps).
// Warp w handles neurons j0 = jg*16 + w*2 + {0,1} for 4 ROIs:
// each w1 element feeds 8 FMAs; 8 independent accumulators for MLP.
// ============================================================
__global__ void __launch_bounds__(256) mlp_kernel(
    const float* __restrict__ w1, const float* __restrict__ b1) {
    __shared__ float r[4 * CC];
    __shared__ float part[8][4];
    const int tid = threadIdx.x, warp = tid >> 5, lane = tid & 31;
    const int roi0 = blockIdx.x * 4;
    const int jg = blockIdx.y;

    for (int i = tid; i < 4 * CC; i += 256)
        r[i] = g_rmean[roi0 * CC + i];          // contiguous, coalesced
    __syncthreads();

    const int j0 = jg * 16 + warp * 2;
    const float* __restrict__ wr0 = w1 + j0 * CC;
    const float* __restrict__ wr1 = wr0 + CC;

    float a00 = 0.f, a01 = 0.f, a02 = 0.f, a03 = 0.f;
    float a10 = 0.f, a11 = 0.f, a12 = 0.f, a13 = 0.f;
    #pragma unroll 4
    for (int k = lane; k < CC; k += 32) {
        float w0 = wr0[k], w1v = wr1[k];
        float v0 = r[k], v1 = r[CC + k], v2 = r[2 * CC + k], v3 = r[3 * CC + k];
        a00 += w0 * v0;  a01 += w0 * v1;  a02 += w0 * v2;  a03 += w0 * v3;
        a10 += w1v * v0; a11 += w1v * v1; a12 += w1v * v2; a13 += w1v * v3;
    }
    #pragma unroll
    for (int o = 16; o; o >>= 1) {
        a00 += __shfl_xor_sync(0xffffffffu, a00, o);
        a01 += __shfl_xor_sync(0xffffffffu, a01, o);
        a02 += __shfl_xor_sync(0xffffffffu, a02, o);
        a03 += __shfl_xor_sync(0xffffffffu, a03, o);
        a10 += __shfl_xor_sync(0xffffffffu, a10, o);
        a11 += __shfl_xor_sync(0xffffffffu, a11, o);
        a12 += __shfl_xor_sync(0xffffffffu, a12, o);
        a13 += __shfl_xor_sync(0xffffffffu, a13, o);
    }
    if (lane == 0) {
        float bj0 = b1[j0], bj1 = b1[j0 + 1];
        float vj0 = g_v[j0], vj1 = g_v[j0 + 1];
        part[warp][0] = vj0 * fmaxf(a00 + bj0, 0.f) + vj1 * fmaxf(a10 + bj1, 0.f);
        part[warp][1] = vj0 * fmaxf(a01 + bj0, 0.f) + vj1 * fmaxf(a11 + bj1, 0.f);
        part[warp][2] = vj0 * fmaxf(a02 + bj0, 0.f) + vj1 * fmaxf(a12 + bj1, 0.f);
        part[warp][3] = vj0 * fmaxf(a03 + bj0, 0.f) + vj1 * fmaxf(a13 + bj1, 0.f);
    }
    __syncthreads();
    if (tid < 4) {
        float s = 0.f;
        #pragma unroll
        for (int w = 0; w < 8; ++w) s += part[w][tid];
        g_part[(roi0 + tid) * 8 + jg] = s;
    }
}

// ============================================================
// Kernel 4: finalize. out[roi] = c0 + sum_jg part[roi][jg].
// ============================================================
__global__ void fin_kernel(float* __restrict__ out) {
    int roi = threadIdx.x;
    float s = g_c0;
    #pragma unroll
    for (int jg = 0; jg < 8; ++jg) s += g_part[roi * 8 + jg];
    out[roi] = s;
}

// ============================================================
// launch
// ============================================================
extern "C" void kernel_launch(void* const* d_in, const int* in_sizes, int n_in,
                              void* d_out, int out_size) {
    const float* x    = (const float*)d_in[0];
    const float* bbox = (const float*)d_in[1];
    const float* w1   = (const float*)d_in[2];
    const float* b1   = (const float*)d_in[3];
    const float* w2   = (const float*)d_in[4];
    const float* b2   = (const float*)d_in[5];
    const float* w3   = (const float*)d_in[6];
    const float* b3   = (const float*)d_in[7];
    float* out = (float*)d_out;

    wmap_kernel<<<RR, 256>>>(bbox);
    prep_kernel<<<2, 128>>>(bbox, w2, b2, w3, b3);
    mean_roi_kernel<<<BB * CC, 256>>>(x);
    mlp_kernel<<<dim3(RR / 4, 8), 256>>>(w1, b1);
    fin_kernel<<<1, RR>>>(out);
}

// round 6
// speedup vs baseline: 1.2395x; 1.0146x over previous
#include <cuda_runtime.h>
#include <cuda_bf16.h>

#define BB 16
#define CC 528
#define TT 32
#define HH 28
#define WW 28
#define HW 784          // 28*28
#define HW4 196         // HW/4  (28 = 4*7 -> rows align to float4 groups, 7 per row)
#define RR 256
#define PLANE_F (TT*HW) // 25088 floats per (b,c)

// ---- device scratch (no allocations allowed) ----
__device__ float g_wmap[RR * HW];     // per-ROI dense weight map over 28x28
__device__ int4  g_rect[RR];          // xmin, xmax, ymin, ymax (inclusive); xmin>xmax => empty
__device__ int   g_list[BB][RR];      // ROI indices per batch
__device__ int   g_cnt[BB];
__device__ float g_rmean[RR * CC];    // pooled ROI features
__device__ float g_v[128];            // folded w3 @ w2   (layers 2+3 are linear)
__device__ float g_c0;                // folded bias
__device__ float g_part[RR * 8];      // per-(roi, j-group) partial sums
__device__ int   g_load[BB][HW4];     // per-batch compacted float4-group indices to load
__device__ int   g_nload[BB];         // count per batch

// ============================================================
// Kernel 0: build per-ROI weight map + nonzero rect.
// ============================================================
__global__ void wmap_kernel(const float* __restrict__ bbox) {
    __shared__ float smap[HW];
    __shared__ int sxmin, sxmax, symin, symax;
    const int roi = blockIdx.x;
    const int tid = threadIdx.x;

    for (int p = tid; p < HW; p += 256) smap[p] = 0.f;
    if (tid == 0) { sxmin = 1000; symin = 1000; sxmax = -1; symax = -1; }
    __syncthreads();

    const float* bb = bbox + roi * 5;
    const float x1 = bb[1] * 0.0625f - 0.5f;
    const float y1 = bb[2] * 0.0625f - 0.5f;
    const float x2 = bb[3] * 0.0625f - 0.5f;
    const float y2 = bb[4] * 0.0625f - 0.5f;
    const float bw = (x2 - x1) * 0.125f;   // /OUT(8)
    const float bh = (y2 - y1) * 0.125f;

    const int iy = tid >> 4, ix = tid & 15;
    const float sy = y1 + ((float)iy * 0.5f + 0.25f) * bh;  // off=(i+0.5)/SR
    const float sx = x1 + ((float)ix * 0.5f + 0.25f) * bw;

    const bool valid = (sy > -1.0f) && (sy < (float)HH) && (sx > -1.0f) && (sx < (float)WW);
    if (valid) {
        float yc = fminf(fmaxf(sy, 0.f), (float)(HH - 1));
        float xc = fminf(fmaxf(sx, 0.f), (float)(WW - 1));
        int y0 = (int)floorf(yc);
        int x0 = (int)floorf(xc);
        int y1i = min(y0 + 1, HH - 1);
        int x1i = min(x0 + 1, WW - 1);
        float ly = yc - (float)y0, lx = xc - (float)x0;
        float hy = 1.f - ly, hx = 1.f - lx;
        const float s = 1.0f / 256.0f;   // uniform mean over 16x16 samples
        atomicAdd(&smap[y0 * WW + x0],  hy * hx * s);
        atomicAdd(&smap[y0 * WW + x1i], hy * lx * s);
        atomicAdd(&smap[y1i * WW + x0], ly * hx * s);
        atomicAdd(&smap[y1i * WW + x1i], ly * lx * s);
        atomicMin(&sxmin, x0); atomicMax(&sxmax, x1i);
        atomicMin(&symin, y0); atomicMax(&symax, y1i);
    }
    __syncthreads();

    for (int p = tid; p < HW; p += 256) g_wmap[roi * HW + p] = smap[p];
    if (tid == 0) g_rect[roi] = make_int4(sxmin, sxmax, symin, symax);
}

// ============================================================
// Kernel 1: per-batch ROI lists + folded v = w3@w2, c0 = w3@b2 + b3.
// ============================================================
__global__ void prep_kernel(const float* __restrict__ bbox,
                            const float* __restrict__ w2,
                            const float* __restrict__ b2,
                            const float* __restrict__ w3,
                            const float* __restrict__ b3) {
    if (blockIdx.x == 0) {
        int b = threadIdx.x;
        if (b < BB) {
            int cnt = 0;
            for (int r = 0; r < RR; ++r) {
                int rb = (int)bbox[r * 5];
                if (rb == b) g_list[b][cnt++] = r;
            }
            g_cnt[b] = cnt;
        }
    } else {
        int j = threadIdx.x;
        if (j < 128) {
            float acc = 0.f;
            #pragma unroll
            for (int i = 0; i < 32; ++i) acc += w3[i] * w2[i * 128 + j];
            g_v[j] = acc;
            if (j == 0) {
                float c = b3[0];
                #pragma unroll
                for (int i = 0; i < 32; ++i) c += w3[i] * b2[i];
                g_c0 = c;
            }
        }
    }
}

// ============================================================
// Kernel 1b: per-batch union of ROI rects at float4-group granularity.
// Only these groups are ever multiplied by nonzero wmap entries, so
// only these need loading from x. One block per batch.
// ============================================================
__global__ void cover_kernel() {
    __shared__ unsigned char mask[HW4];
    const int b = blockIdx.x;
    const int tid = threadIdx.x;

    for (int i = tid; i < HW4; i += 256) mask[i] = 0;
    __syncthreads();

    const int n = g_cnt[b];
    for (int r = 0; r < n; ++r) {
        const int4 rc = g_rect[g_list[b][r]];
        if (rc.x > rc.y) continue;
        const int g0 = rc.x >> 2, g1 = rc.y >> 2;     // col groups (7 per row)
        const int cols = g1 - g0 + 1;
        const int tot = (rc.w - rc.z + 1) * cols;
        for (int i = tid; i < tot; i += 256) {
            int ry = i / cols, cx = i - ry * cols;
            mask[(rc.z + ry) * 7 + g0 + cx] = 1;       // idempotent, no sync needed
        }
    }
    __syncthreads();

    if (tid == 0) {
        int cnt = 0;
        for (int i = 0; i < HW4; ++i)
            if (mask[i]) g_load[b][cnt++] = i;
        g_nload[b] = cnt;
    }
}

// ============================================================
// Kernel 2 (HBM-bound): fused temporal mean + ROI pooling,
// restricted to the batch's covered float4 groups.
// One block per (b,c): 8448 blocks, 256 threads.
// ============================================================
__global__ void __launch_bounds__(256) mean_roi_kernel(const float* __restrict__ x) {
    __shared__ float plane[HW];
    const int blk = blockIdx.x;            // b*CC + c
    const int b = blk / CC;
    const int c = blk - b * CC;
    const int tid = threadIdx.x;

    const float4* __restrict__ xp =
        (const float4*)(x + (size_t)blk * PLANE_F);

    const int n4 = g_nload[b];
    if (tid < n4) {
        const int p4 = g_load[b][tid];     // hot in L2, ~consecutive per warp
        float ax = 0.f, ay = 0.f, az = 0.f, aw = 0.f;
        #pragma unroll
        for (int t = 0; t < TT; ++t) {
            float4 v = __ldcs(&xp[t * HW4 + p4]);   // streaming
            ax += v.x; ay += v.y; az += v.z; aw += v.w;
        }
        const float inv = 1.0f / (float)TT;
        ((float4*)plane)[p4] = make_float4(ax * inv, ay * inv, az * inv, aw * inv);
    }
    __syncthreads();
    // plane entries outside the union are uninitialized but never read:
    // every rect loop below stays inside its own roi's rect, a subset of the union.

    const int nroi = g_cnt[b];
    const int warp = tid >> 5, lane = tid & 31;
    for (int r = warp; r < nroi; r += 8) {
        const int roi = g_list[b][r];
        const int4 rc = g_rect[roi];       // xmin xmax ymin ymax
        float acc = 0.f;
        if (rc.x <= rc.y) {
            // width <= 28 < 32: one element per lane per row
            const int xx = rc.x + lane;
            const bool on = (xx <= rc.y);
            const float* __restrict__ wm = g_wmap + roi * HW;
            for (int yy = rc.z; yy <= rc.w; ++yy) {
                int p = yy * WW + xx;
                if (on) acc += wm[p] * plane[p];
            }
        }
        #pragma unroll
        for (int o = 16; o; o >>= 1) acc += __shfl_xor_sync(0xffffffffu, acc, o);
        if (lane == 0) g_rmean[roi * CC + c] = acc;
    }
}

// ============================================================
// Kernel 3: layer-1 GEMV partials with 8-way j-split for occupancy.
// grid = (64 roi-quads, 8 j-groups), 256 threads (8 warps).
// ============================================================
__global__ void __launch_bounds__(256) mlp_kernel(
    const float* __restrict__ w1, const float* __restrict__ b1) {
    __shared__ float r[4 * CC];
    __shared__ float part[8][4];
    const int tid = threadIdx.x, warp = tid >> 5, lane = tid & 31;
    const int roi0 = blockIdx.x * 4;
    const int jg = blockIdx.y;

    for (int i = tid; i < 4 * CC; i += 256)
        r[i] = g_rmean[roi0 * CC + i];          // contiguous, coalesced
    __syncthreads();

    const int j0 = jg * 16 + warp * 2;
    const float* __restrict__ wr0 = w1 + j0 * CC;
    const float* __restrict__ wr1 = wr0 + CC;

    float a00 = 0.f, a01 = 0.f, a02 = 0.f, a03 = 0.f;
    float a10 = 0.f, a11 = 0.f, a12 = 0.f, a13 = 0.f;
    #pragma unroll 4
    for (int k = lane; k < CC; k += 32) {
        float w0 = wr0[k], w1v = wr1[k];
        float v0 = r[k], v1 = r[CC + k], v2 = r[2 * CC + k], v3 = r[3 * CC + k];
        a00 += w0 * v0;  a01 += w0 * v1;  a02 += w0 * v2;  a03 += w0 * v3;
        a10 += w1v * v0; a11 += w1v * v1; a12 += w1v * v2; a13 += w1v * v3;
    }
    #pragma unroll
    for (int o = 16; o; o >>= 1) {
        a00 += __shfl_xor_sync(0xffffffffu, a00, o);
        a01 += __shfl_xor_sync(0xffffffffu, a01, o);
        a02 += __shfl_xor_sync(0xffffffffu, a02, o);
        a03 += __shfl_xor_sync(0xffffffffu, a03, o);
        a10 += __shfl_xor_sync(0xffffffffu, a10, o);
        a11 += __shfl_xor_sync(0xffffffffu, a11, o);
        a12 += __shfl_xor_sync(0xffffffffu, a12, o);
        a13 += __shfl_xor_sync(0xffffffffu, a13, o);
    }
    if (lane == 0) {
        float bj0 = b1[j0], bj1 = b1[j0 + 1];
        float vj0 = g_v[j0], vj1 = g_v[j0 + 1];
        part[warp][0] = vj0 * fmaxf(a00 + bj0, 0.f) + vj1 * fmaxf(a10 + bj1, 0.f);
        part[warp][1] = vj0 * fmaxf(a01 + bj0, 0.f) + vj1 * fmaxf(a11 + bj1, 0.f);
        part[warp][2] = vj0 * fmaxf(a02 + bj0, 0.f) + vj1 * fmaxf(a12 + bj1, 0.f);
        part[warp][3] = vj0 * fmaxf(a03 + bj0, 0.f) + vj1 * fmaxf(a13 + bj1, 0.f);
    }
    __syncthreads();
    if (tid < 4) {
        float s = 0.f;
        #pragma unroll
        for (int w = 0; w < 8; ++w) s += part[w][tid];
        g_part[(roi0 + tid) * 8 + jg] = s;
    }
}

// ============================================================
// Kernel 4: finalize. out[roi] = c0 + sum_jg part[roi][jg].
// ============================================================
__global__ void fin_kernel(float* __restrict__ out) {
    int roi = threadIdx.x;
    float s = g_c0;
    #pragma unroll
    for (int jg = 0; jg < 8; ++jg) s += g_part[roi * 8 + jg];
    out[roi] = s;
}

// ============================================================
// launch
// ============================================================
extern "C" void kernel_launch(void* const* d_in, const int* in_sizes, int n_in,
                              void* d_out, int out_size) {
    const float* x    = (const float*)d_in[0];
    const float* bbox = (const float*)d_in[1];
    const float* w1   = (const float*)d_in[2];
    const float* b1   = (const float*)d_in[3];
    const float* w2   = (const float*)d_in[4];
    const float* b2   = (const float*)d_in[5];
    const float* w3   = (const float*)d_in[6];
    const float* b3   = (const float*)d_in[7];
    float* out = (float*)d_out;

    wmap_kernel<<<RR, 256>>>(bbox);
    prep_kernel<<<2, 128>>>(bbox, w2, b2, w3, b3);
    cover_kernel<<<BB, 256>>>();
    mean_roi_kernel<<<BB * CC, 256>>>(x);
    mlp_kernel<<<dim3(RR / 4, 8), 256>>>(w1, b1);
    fin_kernel<<<1, RR>>>(out);
}